// round 4
// baseline (speedup 1.0000x reference)
#include <cuda_runtime.h>
#include <cstdint>

#define T_SEQ 512
#define H 32
#define WPB 2          // warps per block in recurrence kernel
#define MAXB 4096

typedef unsigned long long u64;

// scratch: xin[b][t][i] = x[b][t]@W_ih1^T + (b_ih1 + b_hh1)
__device__ float g_xin[(size_t)MAXB * T_SEQ * H];

__device__ __forceinline__ u64 fma2(u64 a, u64 b, u64 c) {
    u64 d;
    asm("fma.rn.f32x2 %0, %1, %2, %3;" : "=l"(d) : "l"(a), "l"(b), "l"(c));
    return d;
}
__device__ __forceinline__ u64 add2(u64 a, u64 b) {
    u64 d;
    asm("add.rn.f32x2 %0, %1, %2;" : "=l"(d) : "l"(a), "l"(b));
    return d;
}
__device__ __forceinline__ float lo_hi_sum(u64 a) {
    unsigned lo, hi;
    asm("mov.b64 {%0,%1}, %2;" : "=r"(lo), "=r"(hi) : "l"(a));
    return __uint_as_float(lo) + __uint_as_float(hi);
}
// tanh(x) = 1 - 2/(exp(2x)+1); exp overflow -> inf -> 1. abs err ~1e-7.
__device__ __forceinline__ float tanh_fast(float x) {
    float e = __expf(2.0f * x);
    return 1.0f - __fdividef(2.0f, e + 1.0f);
}

// ============================================================================
// K1: xin precompute. Lane = output i. x rows read via warp-UNIFORM LDG.128
// (coalescer dedups to 1 wavefront; revisits hit L1). No shared, no syncwarp.
// Each warp: 8 consecutive rows, unrolled x2 for 4 independent FMA chains.
// ============================================================================
__global__ __launch_bounds__(256)
void xin_kernel(const float* __restrict__ x,
                const float* __restrict__ W_ih1,
                const float* __restrict__ b_ih1,
                const float* __restrict__ b_hh1)
{
    const int lane = threadIdx.x & 31;
    const int wid  = threadIdx.x >> 5;
    const long long r0 = ((long long)blockIdx.x * 8 + wid) * 8;

    u64 w[16];
    {
        const u64* p = (const u64*)(W_ih1 + lane * H);
        #pragma unroll
        for (int k = 0; k < 16; k++) w[k] = p[k];
    }
    const float bias = b_ih1[lane] + b_hh1[lane];

    #pragma unroll
    for (int r = 0; r < 8; r += 2) {
        // warp-uniform addresses: every lane reads the same row chunks
        const ulonglong2* xr0 = (const ulonglong2*)(x + (r0 + r) * H);
        const ulonglong2* xr1 = (const ulonglong2*)(x + (r0 + r + 1) * H);
        u64 a0 = 0ull, a1 = 0ull, b0 = 0ull, b1 = 0ull;
        #pragma unroll
        for (int m = 0; m < 8; m++) {
            ulonglong2 v0 = xr0[m];
            ulonglong2 v1 = xr1[m];
            a0 = fma2(v0.x, w[2 * m],     a0);
            a1 = fma2(v0.y, w[2 * m + 1], a1);
            b0 = fma2(v1.x, w[2 * m],     b0);
            b1 = fma2(v1.y, w[2 * m + 1], b1);
        }
        g_xin[(r0 + r)     * H + lane] = lo_hi_sum(add2(a0, a1)) + bias;
        g_xin[(r0 + r + 1) * H + lane] = lo_hi_sum(add2(b0, b1)) + bias;
    }
}

// ============================================================================
// K2: layer-pipelined recurrence. One warp per batch element, lane = unit i.
// Iteration k computes (from the single published buffer [h1_k | h2_{k-1}]):
//    h1_{k+1} = tanh(W_hh1 h1_k + xin_{k+1})
//    h2_k     = tanh(W_ih2 h1_k + W_hh2 h2_{k-1} + b2)
// h1_k read ONCE feeds two matrices; one syncwarp per step.
// ============================================================================
__global__ __launch_bounds__(WPB * 32, 8)
void rnn_rec_kernel(const float* __restrict__ W_hh1,
                    const float* __restrict__ W_ih2,
                    const float* __restrict__ W_hh2,
                    const float* __restrict__ b_ih2,
                    const float* __restrict__ b_hh2,
                    const float* __restrict__ W_fc,
                    const float* __restrict__ b_fc,
                    float* __restrict__ out, int Bn)
{
    const int lane = threadIdx.x & 31;
    const int wid  = threadIdx.x >> 5;
    const int b    = blockIdx.x * WPB + wid;
    if (b >= Bn) return;

    // [warp][pingpong][ h1:0..31 | h2:32..63 ]
    __shared__ __align__(16) float s[WPB][2][2 * H];

    u64 whh1[16], wih2[16], whh2[16];
    {
        const u64* p1 = (const u64*)(W_hh1 + lane * H);
        const u64* p2 = (const u64*)(W_ih2 + lane * H);
        const u64* p3 = (const u64*)(W_hh2 + lane * H);
        #pragma unroll
        for (int k = 0; k < 16; k++) { whh1[k] = p1[k]; wih2[k] = p2[k]; whh2[k] = p3[k]; }
    }
    const float bias2 = b_ih2[lane] + b_hh2[lane];

    const float* xg = g_xin + (size_t)b * T_SEQ * H + lane;

    // prologue: h1_0 = tanh(xin_0), h2_{-1} = 0, published in buffer 1
    s[wid][1][lane]     = tanh_fast(xg[0]);
    s[wid][1][H + lane] = 0.0f;
    __syncwarp();

    // xin stream for indices k+1 (1..511, clamped): 4-ahead rotation
    float nxt0 = xg[1 * H], nxt1 = xg[2 * H], nxt2 = xg[3 * H], nxt3 = xg[4 * H];
    float cur0 = 0.f, cur1 = 0.f, cur2 = 0.f, cur3 = 0.f;

    float h2_last = 0.0f;

    #pragma unroll 4
    for (int k = 0; k < T_SEQ; ++k) {
        const int p = k & 1;

        if ((k & 3) == 0) {
            cur0 = nxt0; cur1 = nxt1; cur2 = nxt2; cur3 = nxt3;
            int i0 = k + 5, i1 = k + 6, i2 = k + 7, i3 = k + 8;
            if (i0 > T_SEQ - 1) i0 = T_SEQ - 1;
            if (i1 > T_SEQ - 1) i1 = T_SEQ - 1;
            if (i2 > T_SEQ - 1) i2 = T_SEQ - 1;
            if (i3 > T_SEQ - 1) i3 = T_SEQ - 1;
            nxt0 = xg[(size_t)i0 * H];
            nxt1 = xg[(size_t)i1 * H];
            nxt2 = xg[(size_t)i2 * H];
            nxt3 = xg[(size_t)i3 * H];
        }
        const float xin_next = ((k & 3) == 0) ? cur0 : ((k & 3) == 1) ? cur1
                             : ((k & 3) == 2) ? cur2 : cur3;

        const ulonglong2* hb = (const ulonglong2*)&s[wid][p ^ 1][0];

        u64 a0 = 0ull, a1 = 0ull;   // W_hh1 . h1_k
        u64 c0 = 0ull, c1 = 0ull;   // W_ih2 . h1_k  (same loaded chunks!)
        #pragma unroll
        for (int m = 0; m < 8; m++) {
            ulonglong2 v = hb[m];
            a0 = fma2(v.x, whh1[2 * m],     a0);
            a1 = fma2(v.y, whh1[2 * m + 1], a1);
            c0 = fma2(v.x, wih2[2 * m],     c0);
            c1 = fma2(v.y, wih2[2 * m + 1], c1);
        }
        u64 d0 = 0ull, d1 = 0ull;   // W_hh2 . h2_{k-1}
        #pragma unroll
        for (int m = 0; m < 8; m++) {
            ulonglong2 v = hb[8 + m];
            d0 = fma2(v.x, whh2[2 * m],     d0);
            d1 = fma2(v.y, whh2[2 * m + 1], d1);
        }

        const float h1n = tanh_fast(lo_hi_sum(add2(a0, a1)) + xin_next);
        const float h2n = tanh_fast(lo_hi_sum(add2(add2(c0, c1), add2(d0, d1))) + bias2);

        s[wid][p][lane]     = h1n;   // h1_{k+1}
        s[wid][p][H + lane] = h2n;   // h2_k
        __syncwarp();

        h2_last = h2n;
    }

    // out[b] = h2_{T-1} . W_fc + b_fc
    float v = h2_last * W_fc[lane];
    #pragma unroll
    for (int o = 16; o; o >>= 1) v += __shfl_xor_sync(0xFFFFFFFFu, v, o);
    if (lane == 0) out[b] = v + b_fc[0];
}

extern "C" void kernel_launch(void* const* d_in, const int* in_sizes, int n_in,
                              void* d_out, int out_size)
{
    const float* x     = (const float*)d_in[0];
    const float* W_ih1 = (const float*)d_in[1];
    const float* W_hh1 = (const float*)d_in[2];
    const float* b_ih1 = (const float*)d_in[3];
    const float* b_hh1 = (const float*)d_in[4];
    const float* W_ih2 = (const float*)d_in[5];
    const float* W_hh2 = (const float*)d_in[6];
    const float* b_ih2 = (const float*)d_in[7];
    const float* b_hh2 = (const float*)d_in[8];
    const float* W_fc  = (const float*)d_in[9];
    const float* b_fc  = (const float*)d_in[10];
    float* out = (float*)d_out;

    const int Bn = in_sizes[0] / (T_SEQ * H);

    // K1: 64 rows per block (8 warps x 8 rows)
    const int rows = Bn * T_SEQ;
    xin_kernel<<<rows / 64, 256>>>(x, W_ih1, b_ih1, b_hh1);

    // K2: layer-pipelined recurrence
    rnn_rec_kernel<<<(Bn + WPB - 1) / WPB, WPB * 32>>>(
        W_hh1, W_ih2, W_hh2, b_ih2, b_hh2, W_fc, b_fc, out, Bn);
}

// round 5
// speedup vs baseline: 2.0582x; 2.0582x over previous
#include <cuda_runtime.h>
#include <cstdint>

#define T_SEQ 512
#define H 32
#define MAXB 4096

typedef unsigned long long u64;

// scratch: xin[b][t][i] = x[b][t]@W_ih1^T + (b_ih1 + b_hh1)
__device__ float g_xin[(size_t)MAXB * T_SEQ * H];

__device__ __forceinline__ u64 fma2(u64 a, u64 b, u64 c) {
    u64 d;
    asm("fma.rn.f32x2 %0, %1, %2, %3;" : "=l"(d) : "l"(a), "l"(b), "l"(c));
    return d;
}
__device__ __forceinline__ u64 add2(u64 a, u64 b) {
    u64 d;
    asm("add.rn.f32x2 %0, %1, %2;" : "=l"(d) : "l"(a), "l"(b));
    return d;
}
__device__ __forceinline__ float lo_hi_sum(u64 a) {
    unsigned lo, hi;
    asm("mov.b64 {%0,%1}, %2;" : "=r"(lo), "=r"(hi) : "l"(a));
    return __uint_as_float(lo) + __uint_as_float(hi);
}
// tanh(x) = 1 - 2/(exp(2x)+1); exp overflow -> inf -> 1. abs err ~1e-7.
__device__ __forceinline__ float tanh_fast(float x) {
    float e = __expf(2.0f * x);
    return 1.0f - __fdividef(2.0f, e + 1.0f);
}

// ============================================================================
// K1: xin precompute. lane = output i. W staged via shared (padded, conflict-
// free), amortized over 64 rows/warp. x broadcast via uniform LDS (1 wf/16B).
// Block = 4 warps = 256 rows. All LDG/STG fully coalesced.
// ============================================================================
__global__ __launch_bounds__(128)
void xin_kernel(const float* __restrict__ x,
                const float* __restrict__ W_ih1,
                const float* __restrict__ b_ih1,
                const float* __restrict__ b_hh1)
{
    const int tid  = threadIdx.x;
    const int lane = tid & 31;
    const int wid  = tid >> 5;

    __shared__ __align__(16) float sw[32][36];          // padded W rows (stride 144B)
    __shared__ __align__(16) float sx[4][2][8 * H];     // per-warp double-buffered 8-row x tile

    // stage W coalesced (1024 floats / 128 threads)
    #pragma unroll
    for (int idx = tid; idx < H * H; idx += 128) sw[idx >> 5][idx & 31] = W_ih1[idx];
    __syncthreads();

    // per-lane weight row from padded shared: stride 144B, 16B aligned, conflict-free
    u64 w[16];
    {
        const u64* wr = (const u64*)&sw[lane][0];
        #pragma unroll
        for (int k = 0; k < 16; k++) w[k] = wr[k];
    }
    const float bias = b_ih1[lane] + b_hh1[lane];

    const long long base = ((long long)blockIdx.x * 4 + wid) * 64;  // 64 rows per warp
    const float* xb = x + base * H;
    float* ob = g_xin + base * H;

    // prefetch group 0 (8 rows = 256 floats; lane takes 2 float4, coalesced)
    float4 p0 = *(const float4*)(xb + lane * 4);
    float4 p1 = *(const float4*)(xb + 128 + lane * 4);

    #pragma unroll
    for (int g = 0; g < 8; g++) {
        const int buf = g & 1;
        *(float4*)&sx[wid][buf][lane * 4]       = p0;
        *(float4*)&sx[wid][buf][128 + lane * 4] = p1;
        if (g < 7) {
            p0 = *(const float4*)(xb + (g + 1) * 256 + lane * 4);
            p1 = *(const float4*)(xb + (g + 1) * 256 + 128 + lane * 4);
        }
        __syncwarp();   // one sync/iter: separates this buf's writes from reads;
                        // double buffering covers the write(g+2) vs read(g) hazard

        #pragma unroll
        for (int rr = 0; rr < 8; rr++) {
            const ulonglong2* xv = (const ulonglong2*)&sx[wid][buf][rr * H];
            u64 a0 = 0ull, a1 = 0ull;
            #pragma unroll
            for (int m = 0; m < 8; m++) {
                ulonglong2 v = xv[m];
                a0 = fma2(v.x, w[2 * m],     a0);
                a1 = fma2(v.y, w[2 * m + 1], a1);
            }
            ob[(g * 8 + rr) * H + lane] = lo_hi_sum(add2(a0, a1)) + bias;
        }
    }
}

// ============================================================================
// K2: layer-pipelined recurrence, TWO batch elements per warp (2x ILP,
// weights amortized). One warp per block. lane = unit i.
//   h1_{k+1} = tanh(W_hh1 h1_k + xin_{k+1})
//   h2_k     = tanh(W_ih2 h1_k + W_hh2 h2_{k-1} + b2)
// ============================================================================
__global__ __launch_bounds__(32, 10)
void rnn_rec_kernel(const float* __restrict__ W_hh1,
                    const float* __restrict__ W_ih2,
                    const float* __restrict__ W_hh2,
                    const float* __restrict__ b_ih2,
                    const float* __restrict__ b_hh2,
                    const float* __restrict__ W_fc,
                    const float* __restrict__ b_fc,
                    float* __restrict__ out, int Bn)
{
    const int lane = threadIdx.x & 31;
    const int b0 = blockIdx.x * 2;
    if (b0 >= Bn) return;
    const int b1 = (b0 + 1 < Bn) ? (b0 + 1) : b0;   // clamp (duplicate compute if odd Bn)

    // [pingpong][ A.h1 | A.h2 | B.h1 | B.h2 ], 32 floats each
    __shared__ __align__(16) float s[2][4 * H];

    u64 whh1[16], wih2[16], whh2[16];
    {
        const u64* p1 = (const u64*)(W_hh1 + lane * H);
        const u64* p2 = (const u64*)(W_ih2 + lane * H);
        const u64* p3 = (const u64*)(W_hh2 + lane * H);
        #pragma unroll
        for (int k = 0; k < 16; k++) { whh1[k] = p1[k]; wih2[k] = p2[k]; whh2[k] = p3[k]; }
    }
    const float bias2 = b_ih2[lane] + b_hh2[lane];

    const float* xA = g_xin + (size_t)b0 * T_SEQ * H + lane;
    const float* xB = g_xin + (size_t)b1 * T_SEQ * H + lane;

    // prologue: h1_0 = tanh(xin_0), h2_{-1}=0, published to buffer 1
    s[1][lane]          = tanh_fast(xA[0]);
    s[1][H + lane]      = 0.0f;
    s[1][2 * H + lane]  = tanh_fast(xB[0]);
    s[1][3 * H + lane]  = 0.0f;
    __syncwarp();

    // xin register queues, depth 4 (consume index k+1 at step k)
    float qA0 = xA[1 * H], qA1 = xA[2 * H], qA2 = xA[3 * H], qA3 = xA[4 * H];
    float qB0 = xB[1 * H], qB1 = xB[2 * H], qB2 = xB[3 * H], qB3 = xB[4 * H];

    float h2A = 0.0f, h2B = 0.0f;

    #pragma unroll 4
    for (int k = 0; k < T_SEQ; ++k) {
        const int p = k & 1;
        const ulonglong2* hp = (const ulonglong2*)&s[p ^ 1][0];

        u64 aA0 = 0ull, aA1 = 0ull, cA0 = 0ull, cA1 = 0ull;
        u64 aB0 = 0ull, aB1 = 0ull, cB0 = 0ull, cB1 = 0ull;
        #pragma unroll
        for (int m = 0; m < 8; m++) {
            ulonglong2 vA = hp[m];          // A.h1_k
            ulonglong2 vB = hp[16 + m];     // B.h1_k
            aA0 = fma2(vA.x, whh1[2 * m],     aA0);
            aA1 = fma2(vA.y, whh1[2 * m + 1], aA1);
            cA0 = fma2(vA.x, wih2[2 * m],     cA0);
            cA1 = fma2(vA.y, wih2[2 * m + 1], cA1);
            aB0 = fma2(vB.x, whh1[2 * m],     aB0);
            aB1 = fma2(vB.y, whh1[2 * m + 1], aB1);
            cB0 = fma2(vB.x, wih2[2 * m],     cB0);
            cB1 = fma2(vB.y, wih2[2 * m + 1], cB1);
        }
        u64 dA0 = 0ull, dA1 = 0ull, dB0 = 0ull, dB1 = 0ull;
        #pragma unroll
        for (int m = 0; m < 8; m++) {
            ulonglong2 vA = hp[8 + m];      // A.h2_{k-1}
            ulonglong2 vB = hp[24 + m];     // B.h2_{k-1}
            dA0 = fma2(vA.x, whh2[2 * m],     dA0);
            dA1 = fma2(vA.y, whh2[2 * m + 1], dA1);
            dB0 = fma2(vB.x, whh2[2 * m],     dB0);
            dB1 = fma2(vB.y, whh2[2 * m + 1], dB1);
        }

        const float h1nA = tanh_fast(lo_hi_sum(add2(aA0, aA1)) + qA0);
        const float h2nA = tanh_fast(lo_hi_sum(add2(add2(cA0, cA1), add2(dA0, dA1))) + bias2);
        const float h1nB = tanh_fast(lo_hi_sum(add2(aB0, aB1)) + qB0);
        const float h2nB = tanh_fast(lo_hi_sum(add2(add2(cB0, cB1), add2(dB0, dB1))) + bias2);

        // rotate queues (renamed away under unroll) + refill at k+5
        qA0 = qA1; qA1 = qA2; qA2 = qA3;
        qB0 = qB1; qB1 = qB2; qB2 = qB3;
        int nk = k + 5; if (nk > T_SEQ - 1) nk = T_SEQ - 1;
        qA3 = xA[(size_t)nk * H];
        qB3 = xB[(size_t)nk * H];

        s[p][lane]         = h1nA;   // h1_{k+1}
        s[p][H + lane]     = h2nA;   // h2_k
        s[p][2 * H + lane] = h1nB;
        s[p][3 * H + lane] = h2nB;
        __syncwarp();

        h2A = h2nA; h2B = h2nB;
    }

    // FC head
    float vA = h2A * W_fc[lane];
    float vB = h2B * W_fc[lane];
    #pragma unroll
    for (int o = 16; o; o >>= 1) {
        vA += __shfl_xor_sync(0xFFFFFFFFu, vA, o);
        vB += __shfl_xor_sync(0xFFFFFFFFu, vB, o);
    }
    if (lane == 0) {
        out[b0] = vA + b_fc[0];
        if (b1 != b0) out[b1] = vB + b_fc[0];
    }
}

extern "C" void kernel_launch(void* const* d_in, const int* in_sizes, int n_in,
                              void* d_out, int out_size)
{
    const float* x     = (const float*)d_in[0];
    const float* W_ih1 = (const float*)d_in[1];
    const float* W_hh1 = (const float*)d_in[2];
    const float* b_ih1 = (const float*)d_in[3];
    const float* b_hh1 = (const float*)d_in[4];
    const float* W_ih2 = (const float*)d_in[5];
    const float* W_hh2 = (const float*)d_in[6];
    const float* b_ih2 = (const float*)d_in[7];
    const float* b_hh2 = (const float*)d_in[8];
    const float* W_fc  = (const float*)d_in[9];
    const float* b_fc  = (const float*)d_in[10];
    float* out = (float*)d_out;

    const int Bn = in_sizes[0] / (T_SEQ * H);

    // K1: 256 rows/block (4 warps x 64 rows); rows = Bn*512 is always a multiple of 256
    const int rows = Bn * T_SEQ;
    xin_kernel<<<rows / 256, 128>>>(x, W_ih1, b_ih1, b_hh1);

    // K2: 1 warp per block, 2 batch elements per warp
    rnn_rec_kernel<<<(Bn + 1) / 2, 32>>>(
        W_hh1, W_ih2, W_hh2, b_ih2, b_hh2, W_fc, b_fc, out, Bn);
}